// round 1
// baseline (speedup 1.0000x reference)
#include <cuda_runtime.h>
#include <math.h>

#define NB 16
#define NT 128
#define NC 64
#define NU 128
#define UNF 6
#define EPSV 1e-8f
#define TCHUNK 16

// Scratch (allocation-free rule: __device__ globals)
__device__ float g_sensN[NB * NT * NU];
__device__ float g_sensD[NB * NT * NU];
__device__ float g_SA[NC * NU];
__device__ float g_SB[NC * NU];
__device__ float g_SW[NC * NU];

__device__ __forceinline__ float tanha(float x) {
    float r;
    asm("tanh.approx.f32 %0, %1;" : "=f"(r) : "f"(x));
    return r;
}

__device__ __forceinline__ float softplusf(float x) {
    // x in ~[0.001, 1] for all uses; log1p(exp(x)) is accurate here
    return log1pf(__expf(x));
}

// ---------------------------------------------------------------------------
// Kernel 0: transform sensory params once:
//   SA = 0.5*sigma_s ; SB = -0.5*sigma_s*mu_s ; SW = softplus(w_s)*erev_s
// ---------------------------------------------------------------------------
__global__ void k_sens_prep(const float* __restrict__ ss,
                            const float* __restrict__ smu,
                            const float* __restrict__ sw,
                            const float* __restrict__ serev) {
    int idx = blockIdx.x * blockDim.x + threadIdx.x;
    if (idx < NC * NU) {
        float a = 0.5f * ss[idx];
        g_SA[idx] = a;
        g_SB[idx] = -a * smu[idx];
        g_SW[idx] = softplusf(sw[idx]) * serev[idx];
    }
}

// ---------------------------------------------------------------------------
// Kernel 1: sensory pre-pass. Fully parallel over (b, t).
//   w_num_s[b,t,j] = sum_i SW*(0.5+0.5*tanh(SA*xt + SB)) with sign folded in SW
//   w_den_s[b,t,j] = sum_i |SW|*(0.5+0.5*tanh(...))
// Grid: NB*(NT/TCHUNK) blocks x 128 threads, params staged in smem.
// ---------------------------------------------------------------------------
__global__ void __launch_bounds__(128) k_sensory(const float* __restrict__ x,
                                                 const float* __restrict__ iw,
                                                 const float* __restrict__ ib) {
    extern __shared__ float sm[];
    float* sSA = sm;
    float* sSB = sm + NC * NU;
    float* sSW = sm + 2 * NC * NU;
    float* xb  = sm + 3 * NC * NU;  // TCHUNK*NC

    int b  = blockIdx.x / (NT / TCHUNK);
    int t0 = (blockIdx.x % (NT / TCHUNK)) * TCHUNK;
    int tid = threadIdx.x;

    for (int idx = tid; idx < NC * NU; idx += 128) {
        sSA[idx] = g_SA[idx];
        sSB[idx] = g_SB[idx];
        sSW[idx] = g_SW[idx];
    }
    for (int idx = tid; idx < TCHUNK * NC; idx += 128) {
        int tt = idx / NC, i = idx % NC;
        xb[idx] = fmaf(x[(b * NT + t0 + tt) * NC + i], iw[i], ib[i]);
    }
    __syncthreads();

    int j = tid;
    for (int tt = 0; tt < TCHUNK; tt++) {
        float wn = 0.f, wd = 0.f;
#pragma unroll 8
        for (int i = 0; i < NC; i++) {
            float xv = xb[tt * NC + i];
            float y  = fmaf(sSA[i * NU + j], xv, sSB[i * NU + j]);
            float s  = fmaf(0.5f, tanha(y), 0.5f);
            float we = sSW[i * NU + j];
            wn = fmaf(we, s, wn);
            wd = fmaf(fabsf(we), s, wd);
        }
        int o = (b * NT + t0 + tt) * NU + j;
        g_sensN[o] = wn;
        g_sensD[o] = wd;
    }
}

// ---------------------------------------------------------------------------
// Kernel 2: main recurrence. One CTA per batch element, 128 threads (thread j
// owns post-unit j). Params transformed into smem once:
//   A = 0.5*sigma, B = -0.5*sigma*mu, WE = softplus(w)*erev  (layout [i/4][j][4])
// Per unfold: num2 = sum_i WE*tanh(A*v_i+B), den2 = sum_i |WE|*tanh(...),
//   v = (cm_t*v + K1 + 0.5*num2 + wns) / (K2 + 0.5*den2 + wds)
// with K1 = gl*vleak + 0.5*sum(WE), K2 = cm_t + gl + 0.5*sum|WE| + eps.
// Single __syncthreads per unfold via double-buffered v in smem.
// ---------------------------------------------------------------------------
__global__ void __launch_bounds__(128, 1) k_main(
    const float* __restrict__ h0,
    const float* __restrict__ gleak,
    const float* __restrict__ vleak,
    const float* __restrict__ cm,
    const float* __restrict__ sigma,
    const float* __restrict__ mu,
    const float* __restrict__ w,
    const float* __restrict__ erev,
    const float* __restrict__ ow,
    const float* __restrict__ ob,
    float* __restrict__ out,
    int write_hfinal) {
    extern __shared__ float sm[];
    float* sA = sm;             // 16384 floats
    float* sB = sm + 16384;
    float* sW = sm + 32768;
    float* vb = sm + 49152;     // 2*128

    int b = blockIdx.x;
    int j = threadIdx.x;

    // Prologue: transform recurrent params into smem (coalesced global reads)
    for (int idx = j; idx < NU * NU; idx += NU) {
        int i  = idx >> 7;
        int jj = idx & 127;
        float sg = sigma[idx];
        float a  = 0.5f * sg;
        float bc = -a * mu[idx];
        float we = softplusf(w[idx]) * erev[idx];
        int off = ((i >> 2) * NU + jj) * 4 + (i & 3);
        sA[off] = a;
        sB[off] = bc;
        sW[off] = we;
    }
    float gl  = softplusf(gleak[j]);
    float cmt = softplusf(cm[j]) * (float)UNF;
    __syncthreads();

    // Per-post-unit constants (column sums of WE, |WE|)
    float sumWE = 0.f, sumWA = 0.f;
    for (int i = 0; i < NU; i++) {
        float we = sW[((i >> 2) * NU + j) * 4 + (i & 3)];
        sumWE += we;
        sumWA += fabsf(we);
    }
    float K1 = fmaf(gl, vleak[j], 0.5f * sumWE);
    float K2 = cmt + gl + 0.5f * sumWA + EPSV;
    float owj = ow[j], obj = ob[j];

    float vloc = h0[b * NU + j];
    vb[j] = vloc;
    __syncthreads();

    const float4* A4 = (const float4*)sA;
    const float4* B4 = (const float4*)sB;
    const float4* W4 = (const float4*)sW;

    int p = 0;
#pragma unroll 1
    for (int t = 0; t < NT; t++) {
        int so = (b * NT + t) * NU + j;
        float wns = g_sensN[so];
        float wds = g_sensD[so];
#pragma unroll 1
        for (int u = 0; u < UNF; u++) {
            const float4* v4 = (const float4*)(vb + p * NU);
            float n2 = 0.f, d2 = 0.f;
#pragma unroll
            for (int i4 = 0; i4 < NU / 4; i4++) {
                float4 vv = v4[i4];
                float4 a  = A4[i4 * NU + j];
                float4 bc = B4[i4 * NU + j];
                float4 we = W4[i4 * NU + j];
                float t0 = tanha(fmaf(a.x, vv.x, bc.x));
                float t1 = tanha(fmaf(a.y, vv.y, bc.y));
                float t2 = tanha(fmaf(a.z, vv.z, bc.z));
                float t3 = tanha(fmaf(a.w, vv.w, bc.w));
                n2 = fmaf(we.x, t0, n2);
                d2 = fmaf(fabsf(we.x), t0, d2);
                n2 = fmaf(we.y, t1, n2);
                d2 = fmaf(fabsf(we.y), t1, d2);
                n2 = fmaf(we.z, t2, n2);
                d2 = fmaf(fabsf(we.z), t2, d2);
                n2 = fmaf(we.w, t3, n2);
                d2 = fmaf(fabsf(we.w), t3, d2);
            }
            float num = fmaf(cmt, vloc, K1) + fmaf(0.5f, n2, wns);
            float den = K2 + fmaf(0.5f, d2, wds);
            vloc = __fdividef(num, den);
            vb[(p ^ 1) * NU + j] = vloc;
            __syncthreads();
            p ^= 1;
        }
        out[so] = fmaf(vloc, owj, obj);
    }
    if (write_hfinal) {
        out[NB * NT * NU + b * NU + j] = vloc;
    }
}

// ---------------------------------------------------------------------------
extern "C" void kernel_launch(void* const* d_in, const int* in_sizes, int n_in,
                              void* d_out, int out_size) {
    const float* x      = (const float*)d_in[0];
    const float* h0     = (const float*)d_in[1];
    const float* gleak  = (const float*)d_in[2];
    const float* vleak  = (const float*)d_in[3];
    const float* cm     = (const float*)d_in[4];
    const float* sigma  = (const float*)d_in[5];
    const float* mu     = (const float*)d_in[6];
    const float* w      = (const float*)d_in[7];
    const float* erev   = (const float*)d_in[8];
    const float* ss     = (const float*)d_in[9];
    const float* smu    = (const float*)d_in[10];
    const float* sw     = (const float*)d_in[11];
    const float* serev  = (const float*)d_in[12];
    const float* iw     = (const float*)d_in[13];
    const float* ibias  = (const float*)d_in[14];
    const float* outw   = (const float*)d_in[15];
    const float* outb   = (const float*)d_in[16];

    const int SENS_SMEM = (3 * NC * NU + TCHUNK * NC) * (int)sizeof(float);   // 100 KB
    const int MAIN_SMEM = (3 * NU * NU + 2 * NU) * (int)sizeof(float);        // ~193 KB

    cudaFuncSetAttribute(k_sensory, cudaFuncAttributeMaxDynamicSharedMemorySize, SENS_SMEM);
    cudaFuncSetAttribute(k_main, cudaFuncAttributeMaxDynamicSharedMemorySize, MAIN_SMEM);

    int write_hfinal = (out_size >= NB * NT * NU + NB * NU) ? 1 : 0;

    k_sens_prep<<<(NC * NU + 255) / 256, 256>>>(ss, smu, sw, serev);
    k_sensory<<<NB * (NT / TCHUNK), 128, SENS_SMEM>>>(x, iw, ibias);
    k_main<<<NB, 128, MAIN_SMEM>>>(h0, gleak, vleak, cm, sigma, mu, w, erev,
                                   outw, outb, (float*)d_out, write_hfinal);
}

// round 2
// speedup vs baseline: 1.2790x; 1.2790x over previous
#include <cuda_runtime.h>
#include <cuda_fp16.h>
#include <math.h>

#define NB 16
#define NT 128
#define NC 64
#define NU 128
#define UNF 6
#define EPSV 1e-8f
#define TCHUNK 16

// Scratch (allocation-free rule: __device__ globals)
__device__ float g_sensN[NB * NT * NU];
__device__ float g_sensD[NB * NT * NU];
__device__ float g_SA[NC * NU];
__device__ float g_SB[NC * NU];
__device__ float g_SW[NC * NU];

__device__ __forceinline__ float tanha(float x) {
    float r;
    asm("tanh.approx.f32 %0, %1;" : "=f"(r) : "f"(x));
    return r;
}

__device__ __forceinline__ __half2 tanh2(__half2 x) {
    unsigned xi = *reinterpret_cast<unsigned*>(&x), ri;
    asm("tanh.approx.f16x2 %0, %1;" : "=r"(ri) : "r"(xi));
    return *reinterpret_cast<__half2*>(&ri);
}

__device__ __forceinline__ float softplusf(float x) {
    return log1pf(__expf(x));
}

// ---------------------------------------------------------------------------
// Kernel 0: transform sensory params once (fp32; sensory path keeps full prec)
// ---------------------------------------------------------------------------
__global__ void k_sens_prep(const float* __restrict__ ss,
                            const float* __restrict__ smu,
                            const float* __restrict__ sw,
                            const float* __restrict__ serev) {
    int idx = blockIdx.x * blockDim.x + threadIdx.x;
    if (idx < NC * NU) {
        float a = 0.5f * ss[idx];
        g_SA[idx] = a;
        g_SB[idx] = -a * smu[idx];
        g_SW[idx] = softplusf(sw[idx]) * serev[idx];
    }
}

// ---------------------------------------------------------------------------
// Kernel 1: sensory pre-pass (fp32, fully parallel over b,t)
// ---------------------------------------------------------------------------
__global__ void __launch_bounds__(128) k_sensory(const float* __restrict__ x,
                                                 const float* __restrict__ iw,
                                                 const float* __restrict__ ib) {
    extern __shared__ float sm[];
    float* sSA = sm;
    float* sSB = sm + NC * NU;
    float* sSW = sm + 2 * NC * NU;
    float* xb  = sm + 3 * NC * NU;  // TCHUNK*NC

    int b  = blockIdx.x / (NT / TCHUNK);
    int t0 = (blockIdx.x % (NT / TCHUNK)) * TCHUNK;
    int tid = threadIdx.x;

    for (int idx = tid; idx < NC * NU; idx += 128) {
        sSA[idx] = g_SA[idx];
        sSB[idx] = g_SB[idx];
        sSW[idx] = g_SW[idx];
    }
    for (int idx = tid; idx < TCHUNK * NC; idx += 128) {
        int tt = idx / NC, i = idx % NC;
        xb[idx] = fmaf(x[(b * NT + t0 + tt) * NC + i], iw[i], ib[i]);
    }
    __syncthreads();

    int j = tid;
    for (int tt = 0; tt < TCHUNK; tt++) {
        float wn = 0.f, wd = 0.f;
#pragma unroll 8
        for (int i = 0; i < NC; i++) {
            float xv = xb[tt * NC + i];
            float y  = fmaf(sSA[i * NU + j], xv, sSB[i * NU + j]);
            float s  = fmaf(0.5f, tanha(y), 0.5f);
            float we = sSW[i * NU + j];
            wn = fmaf(we, s, wn);
            wd = fmaf(fabsf(we), s, wd);
        }
        int o = (b * NT + t0 + tt) * NU + j;
        g_sensN[o] = wn;
        g_sensD[o] = wd;
    }
}

// ---------------------------------------------------------------------------
// Kernel 2: main recurrence. 1 CTA / batch, 128 threads (thread j = post-unit).
// Recurrent params live in REGISTERS as half2 pairs over pre-units:
//   a2 = 0.5*sigma, b2 = -0.5*sigma*mu, we2 = softplus(w)*erev   (3*64 regs)
// Per unfold, thread j computes (f16x2 SIMD, chunked fp32 accumulation):
//   q = sum_i we*tanh(a*v_i + b),  r = sum_i |we|*tanh(...)
//   v_j = (cmt*v_j + K1 + wns + 0.5*q) / (K2 + wds + 0.5*r)
// with K1 = gl*vleak + 0.5*sum(WE), K2 = cmt + gl + 0.5*sum|WE| + eps
// (sums taken over the fp16-quantized WE for self-consistency).
// ---------------------------------------------------------------------------
__global__ void __launch_bounds__(128, 1) k_main(
    const float* __restrict__ h0,
    const float* __restrict__ gleak,
    const float* __restrict__ vleak,
    const float* __restrict__ cm,
    const float* __restrict__ sigma,
    const float* __restrict__ mu,
    const float* __restrict__ w,
    const float* __restrict__ erev,
    const float* __restrict__ ow,
    const float* __restrict__ ob,
    float* __restrict__ out,
    int write_hfinal) {
    extern __shared__ char smraw[];
    // Staging for param transform (dead after prologue): 3 * 64*128 half2
    __half* sA = (__half*)smraw;                    // NU*NU halves = 32KB
    __half* sB = sA + NU * NU;
    __half* sW = sB + NU * NU;
    __half* vh = sW + NU * NU;                      // 2*NU halves (double buffer)

    int b = blockIdx.x;
    int j = threadIdx.x;

    // ---- Prologue: transform params, stage as [i/2][j] half2 pairs ----
    for (int k = 0; k < NU; k++) {
        int idx = k * NU + j;
        float sg = sigma[idx];
        float a  = 0.5f * sg;
        float bc = -a * mu[idx];
        float we = softplusf(w[idx]) * erev[idx];
        int off = ((k >> 1) * NU + j) * 2 + (k & 1);
        sA[off] = __float2half(a);
        sB[off] = __float2half(bc);
        sW[off] = __float2half(we);
    }
    float gl  = softplusf(gleak[j]);
    float cmt = softplusf(cm[j]) * (float)UNF;
    __syncthreads();

    // ---- Load this thread's param column into registers ----
    __half2 a2[NU / 2], b2[NU / 2], we2[NU / 2];
    const __half2* pA = (const __half2*)sA;
    const __half2* pB = (const __half2*)sB;
    const __half2* pW = (const __half2*)sW;
#pragma unroll
    for (int i2 = 0; i2 < NU / 2; i2++) {
        a2[i2]  = pA[i2 * NU + j];
        b2[i2]  = pB[i2 * NU + j];
        we2[i2] = pW[i2 * NU + j];
    }

    // Per-post-unit constants from the quantized weights
    float sumWE = 0.f, sumWA = 0.f;
#pragma unroll
    for (int i2 = 0; i2 < NU / 2; i2++) {
        float2 wf = __half22float2(we2[i2]);
        sumWE += wf.x + wf.y;
        sumWA += fabsf(wf.x) + fabsf(wf.y);
    }
    float K1 = fmaf(gl, vleak[j], 0.5f * sumWE);
    float K2 = cmt + gl + 0.5f * sumWA + EPSV;
    float owj = ow[j], obj = ob[j];

    float vloc = h0[b * NU + j];
    vh[j] = __float2half(vloc);
    __syncthreads();

    int p = 0;
#pragma unroll 1
    for (int t = 0; t < NT; t++) {
        int so = (b * NT + t) * NU + j;
        float base_n = K1 + g_sensN[so];
        float base_d = K2 + g_sensD[so];
#pragma unroll 1
        for (int u = 0; u < UNF; u++) {
            const __half2* v2 = (const __half2*)(vh + p * NU);
            float qf = 0.f, rf = 0.f;
#pragma unroll
            for (int c = 0; c < 8; c++) {
                __half2 qh = __float2half2_rn(0.f);
                __half2 rh = __float2half2_rn(0.f);
#pragma unroll
                for (int k = 0; k < 8; k++) {
                    int i2 = c * 8 + k;
                    __half2 vv = v2[i2];
                    __half2 y  = __hfma2(a2[i2], vv, b2[i2]);
                    __half2 th = tanh2(y);
                    qh = __hfma2(we2[i2], th, qh);
                    rh = __hfma2(__habs2(we2[i2]), th, rh);
                }
                float2 tq = __half22float2(qh); qf += tq.x + tq.y;
                float2 tr = __half22float2(rh); rf += tr.x + tr.y;
            }
            float num = fmaf(cmt, vloc, base_n) + 0.5f * qf;
            float den = base_d + 0.5f * rf;
            vloc = __fdividef(num, den);
            vh[(p ^ 1) * NU + j] = __float2half(vloc);
            __syncthreads();
            p ^= 1;
        }
        out[so] = fmaf(vloc, owj, obj);
    }
    if (write_hfinal) {
        out[NB * NT * NU + b * NU + j] = vloc;
    }
}

// ---------------------------------------------------------------------------
extern "C" void kernel_launch(void* const* d_in, const int* in_sizes, int n_in,
                              void* d_out, int out_size) {
    const float* x      = (const float*)d_in[0];
    const float* h0     = (const float*)d_in[1];
    const float* gleak  = (const float*)d_in[2];
    const float* vleak  = (const float*)d_in[3];
    const float* cm     = (const float*)d_in[4];
    const float* sigma  = (const float*)d_in[5];
    const float* mu     = (const float*)d_in[6];
    const float* w      = (const float*)d_in[7];
    const float* erev   = (const float*)d_in[8];
    const float* ss     = (const float*)d_in[9];
    const float* smu    = (const float*)d_in[10];
    const float* sw     = (const float*)d_in[11];
    const float* serev  = (const float*)d_in[12];
    const float* iw     = (const float*)d_in[13];
    const float* ibias  = (const float*)d_in[14];
    const float* outw   = (const float*)d_in[15];
    const float* outb   = (const float*)d_in[16];

    const int SENS_SMEM = (3 * NC * NU + TCHUNK * NC) * (int)sizeof(float);      // 100 KB
    const int MAIN_SMEM = (3 * NU * NU + 2 * NU) * (int)sizeof(__half);          // ~96.5 KB

    cudaFuncSetAttribute(k_sensory, cudaFuncAttributeMaxDynamicSharedMemorySize, SENS_SMEM);
    cudaFuncSetAttribute(k_main, cudaFuncAttributeMaxDynamicSharedMemorySize, MAIN_SMEM);

    int write_hfinal = (out_size >= NB * NT * NU + NB * NU) ? 1 : 0;

    k_sens_prep<<<(NC * NU + 255) / 256, 256>>>(ss, smu, sw, serev);
    k_sensory<<<NB * (NT / TCHUNK), 128, SENS_SMEM>>>(x, iw, ibias);
    k_main<<<NB, 128, MAIN_SMEM>>>(h0, gleak, vleak, cm, sigma, mu, w, erev,
                                   outw, outb, (float*)d_out, write_hfinal);
}